// round 1
// baseline (speedup 1.0000x reference)
#include <cuda_runtime.h>
#include <math.h>

#define NWV 4
#define STEPV 16
#define TTV 512
#define DDV 64
#define NPAIR 60      // NW * (STEP-1)
#define NGRP 44       // NW * 11
#define BIGV 1000000000.0f
#define GAMMAV 5.0f
#define INVG 0.2f

// -------- device scratch (static globals; no runtime allocation) --------
__device__ float g_cost[(size_t)NPAIR * TTV * TTV];   // ~63 MB
__device__ float g_norms[NWV * STEPV * TTV];
__device__ float g_G[NGRP * NGRP];
__device__ float g_sdt[NPAIR];
__device__ float g_mmds[9];

__constant__ int c_pi[9] = {0,0,0,1,1,2,2,3,3};
__constant__ int c_pj[9] = {1,2,3,2,3,1,3,1,2};

// ======================= K0: per-row squared norms =======================
// 64*512 rows of length 64; one warp per row.
__global__ void norms_kernel(const float* __restrict__ data) {
    int gw   = (blockIdx.x * blockDim.x + threadIdx.x) >> 5;
    int lane = threadIdx.x & 31;
    if (gw >= NWV * STEPV * TTV) return;
    const float* row = data + (size_t)gw * DDV;
    float a = row[lane], b = row[lane + 32];
    float s = a * a + b * b;
    #pragma unroll
    for (int o = 16; o > 0; o >>= 1) s += __shfl_down_sync(0xffffffffu, s, o);
    if (lane == 0) g_norms[gw] = s;
}

// ======================= K1: cost matrices =======================
// cost[p][i][s] = |anchor_i|^2 + |other_s|^2 - 2*dot(anchor_i, other_s)
// 64x64 tiles, 256 threads, 4x4 register blocking.
__global__ __launch_bounds__(256) void cost_kernel(const float* __restrict__ data,
                                                   const int* __restrict__ lens) {
    int p  = blockIdx.z;
    int w  = p / 15;
    int jj = p % 15;
    int la = lens[w * STEPV];
    int lb = lens[w * STEPV + 1 + jj];
    int row0 = blockIdx.y * 64;
    int col0 = blockIdx.x * 64;
    if (row0 >= la || col0 >= lb) return;

    const float* A = data + (size_t)(w * STEPV) * TTV * DDV;
    const float* B = data + (size_t)(w * STEPV + 1 + jj) * TTV * DDV;

    __shared__ float As[64][65];
    __shared__ float Bs[64][65];

    int tid = threadIdx.x;
    #pragma unroll
    for (int q = 0; q < 4; q++) {
        int idx = tid + q * 256;        // float4 index: 0..1023
        int r   = idx >> 4;             // row in tile
        int c4  = idx & 15;             // float4 column
        float4 va = *(const float4*)(A + (size_t)(row0 + r) * DDV + c4 * 4);
        float4 vb = *(const float4*)(B + (size_t)(col0 + r) * DDV + c4 * 4);
        As[r][c4*4+0] = va.x; As[r][c4*4+1] = va.y; As[r][c4*4+2] = va.z; As[r][c4*4+3] = va.w;
        Bs[r][c4*4+0] = vb.x; Bs[r][c4*4+1] = vb.y; Bs[r][c4*4+2] = vb.z; Bs[r][c4*4+3] = vb.w;
    }
    __syncthreads();

    int tx = tid & 15, ty = tid >> 4;
    float acc[4][4];
    #pragma unroll
    for (int i = 0; i < 4; i++)
        #pragma unroll
        for (int j = 0; j < 4; j++) acc[i][j] = 0.0f;

    #pragma unroll 8
    for (int k = 0; k < 64; k++) {
        float a0 = As[ty*4+0][k], a1 = As[ty*4+1][k], a2 = As[ty*4+2][k], a3 = As[ty*4+3][k];
        float b0 = Bs[tx*4+0][k], b1 = Bs[tx*4+1][k], b2 = Bs[tx*4+2][k], b3 = Bs[tx*4+3][k];
        acc[0][0] = fmaf(a0,b0,acc[0][0]); acc[0][1] = fmaf(a0,b1,acc[0][1]);
        acc[0][2] = fmaf(a0,b2,acc[0][2]); acc[0][3] = fmaf(a0,b3,acc[0][3]);
        acc[1][0] = fmaf(a1,b0,acc[1][0]); acc[1][1] = fmaf(a1,b1,acc[1][1]);
        acc[1][2] = fmaf(a1,b2,acc[1][2]); acc[1][3] = fmaf(a1,b3,acc[1][3]);
        acc[2][0] = fmaf(a2,b0,acc[2][0]); acc[2][1] = fmaf(a2,b1,acc[2][1]);
        acc[2][2] = fmaf(a2,b2,acc[2][2]); acc[2][3] = fmaf(a2,b3,acc[2][3]);
        acc[3][0] = fmaf(a3,b0,acc[3][0]); acc[3][1] = fmaf(a3,b1,acc[3][1]);
        acc[3][2] = fmaf(a3,b2,acc[3][2]); acc[3][3] = fmaf(a3,b3,acc[3][3]);
    }

    float an[4], bn[4];
    #pragma unroll
    for (int i = 0; i < 4; i++) an[i] = g_norms[(w * STEPV) * TTV + row0 + ty*4 + i];
    #pragma unroll
    for (int j = 0; j < 4; j++) bn[j] = g_norms[(w * STEPV + 1 + jj) * TTV + col0 + tx*4 + j];

    float* Dp = g_cost + (size_t)p * TTV * TTV;
    #pragma unroll
    for (int i = 0; i < 4; i++) {
        float4 v;
        v.x = an[i] + bn[0] - 2.0f * acc[i][0];
        v.y = an[i] + bn[1] - 2.0f * acc[i][1];
        v.z = an[i] + bn[2] - 2.0f * acc[i][2];
        v.w = an[i] + bn[3] - 2.0f * acc[i][3];
        *(float4*)(Dp + (size_t)(row0 + ty*4 + i) * TTV + col0 + tx*4) = v;
    }
}

// ======================= K2: soft-DTW wavefront =======================
// One block per pair; thread i owns row i. Restricted to i<la, j<lb (exact:
// target cell (la-1,lb-1) only depends on smaller indices).
__global__ __launch_bounds__(512) void dtw_kernel(const int* __restrict__ lens) {
    int p  = blockIdx.x;
    int w  = p / 15;
    int jj = p % 15;
    int la = lens[w * STEPV];
    int lb = lens[w * STEPV + 1 + jj];
    const float* Dp = g_cost + (size_t)p * TTV * TTV;

    __shared__ float R[3][TTV];
    int i = threadIdx.x;
    R[0][i] = BIGV; R[1][i] = BIGV; R[2][i] = BIGV;
    float left = BIGV;                       // own value on previous diagonal
    const float* myrow = Dp + (size_t)i * TTV;
    int kmax = la + lb - 2;
    __syncthreads();

    for (int k = 0; k <= kmax; k++) {
        int b0 = k % 3;                      // write: diag k
        int b1 = (k + 2) % 3;                // read : diag k-1
        int b2 = (k + 1) % 3;                // read : diag k-2
        int j  = k - i;
        bool valid = (i < la) && (j >= 0) && (j < lb);
        float up = (i > 0) ? R[b1][i - 1] : BIGV;
        float dg = (i > 0) ? R[b2][i - 1] : ((k == 0) ? 0.0f : BIGV);
        float r = BIGV;
        if (valid) {
            float d  = __ldg(myrow + j);
            float mn = fminf(fminf(dg, up), left);
            float s  = __expf((mn - dg) * INVG)
                     + __expf((mn - up) * INVG)
                     + __expf((mn - left) * INVG);
            r = d + mn - GAMMAV * __logf(s);
        }
        R[b0][i] = r;
        left = r;
        __syncthreads();
    }
    if (i == la - 1) g_sdt[p] = left;        // cell (la-1, lb-1)
}

// ======================= K3: global Gram of 44 group vectors =======================
// 4x4 blocks over the 44x44 Gram, dot length 32768 (float4).
__global__ __launch_bounds__(256) void gram_kernel(const float* __restrict__ data) {
    int bi = blockIdx.y, bj = blockIdx.x;    // 0..10 each
    const float4* pa[4];
    const float4* pb[4];
    #pragma unroll
    for (int a = 0; a < 4; a++) {
        int g  = bi * 4 + a;
        int dr = (g / 11) * STEPV + (g % 11);
        pa[a] = (const float4*)(data + (size_t)dr * TTV * DDV);
        int g2  = bj * 4 + a;
        int dr2 = (g2 / 11) * STEPV + (g2 % 11);
        pb[a] = (const float4*)(data + (size_t)dr2 * TTV * DDV);
    }
    int tid = threadIdx.x;
    float acc[4][4];
    #pragma unroll
    for (int a = 0; a < 4; a++)
        #pragma unroll
        for (int b = 0; b < 4; b++) acc[a][b] = 0.0f;

    const int NV4 = TTV * DDV / 4;           // 8192
    for (int it = tid; it < NV4; it += 256) {
        float4 xa[4], xb[4];
        #pragma unroll
        for (int a = 0; a < 4; a++) xa[a] = pa[a][it];
        #pragma unroll
        for (int b = 0; b < 4; b++) xb[b] = pb[b][it];
        #pragma unroll
        for (int a = 0; a < 4; a++)
            #pragma unroll
            for (int b = 0; b < 4; b++) {
                float t = fmaf(xa[a].x, xb[b].x, fmaf(xa[a].y, xb[b].y,
                          fmaf(xa[a].z, xb[b].z, xa[a].w * xb[b].w)));
                acc[a][b] += t;
            }
    }

    __shared__ float red[256];
    #pragma unroll 1
    for (int a = 0; a < 4; a++)
        #pragma unroll 1
        for (int b = 0; b < 4; b++) {
            __syncthreads();
            red[tid] = acc[a][b];
            __syncthreads();
            for (int s = 128; s > 0; s >>= 1) {
                if (tid < s) red[tid] += red[tid + s];
                __syncthreads();
            }
            if (tid == 0) g_G[(bi * 4 + a) * NGRP + (bj * 4 + b)] = red[0];
        }
}

// ======================= K4: per-pair MMD from Gram =======================
__global__ __launch_bounds__(128) void mmd_kernel() {
    int p  = blockIdx.x;                     // 0..8
    int wa = c_pi[p], wb = c_pj[p];
    __shared__ float l2s[484];
    __shared__ float red[128];
    int tid = threadIdx.x;

    float part = 0.0f;
    for (int e = tid; e < 484; e += 128) {
        int a = e / 22, b = e % 22;
        int ga = (a < 11) ? wa * 11 + a : wb * 11 + (a - 11);
        int gb = (b < 11) ? wa * 11 + b : wb * 11 + (b - 11);
        float l2 = g_G[ga * NGRP + ga] + g_G[gb * NGRP + gb] - 2.0f * g_G[ga * NGRP + gb];
        l2s[e] = l2;
        part += l2;
    }
    red[tid] = part;
    __syncthreads();
    for (int s = 64; s > 0; s >>= 1) {
        if (tid < s) red[tid] += red[tid + s];
        __syncthreads();
    }
    float bw = red[0] / (22.0f * 22.0f - 22.0f) / 4.0f;   // / KMUL^(KNUM//2)
    __syncthreads();

    float part2 = 0.0f;
    for (int e = tid; e < 121; e += 128) {
        int u = e / 11, v = e % 11;
        float lxx = l2s[u * 22 + v];
        float lyy = l2s[(u + 11) * 22 + (v + 11)];
        float lxy = l2s[u * 22 + (v + 11)];
        float lyx = l2s[(u + 11) * 22 + v];
        float t = 0.0f;
        #pragma unroll
        for (int kk = 0; kk < 5; kk++) {
            float ib = 1.0f / (bw * (float)(1 << kk));
            t += __expf(-lxx * ib) + __expf(-lyy * ib)
               - __expf(-lxy * ib) - __expf(-lyx * ib);
        }
        part2 += t;
    }
    red[tid] = part2;
    __syncthreads();
    for (int s = 64; s > 0; s >>= 1) {
        if (tid < s) red[tid] += red[tid + s];
        __syncthreads();
    }
    if (tid == 0) g_mmds[p] = red[0] / 121.0f;
}

// ======================= K5: finalize =======================
__global__ void final_kernel(const int* __restrict__ lens, float* __restrict__ out) {
    if (threadIdx.x != 0 || blockIdx.x != 0) return;
    float total = 0.0f;
    for (int w = 0; w < NWV; w++) {
        float la = (float)lens[w * STEPV];
        float dg[6], dn[9];
        for (int j = 0; j < 15; j++) {
            float lb = (float)lens[w * STEPV + 1 + j];
            float dist = g_sdt[w * 15 + j] / (la + lb);
            if (j < 6) dg[j] = dist; else dn[j - 6] = dist;
        }
        float ca = 0.0f;
        for (int j = 0; j < 6; j++) ca += dg[j];
        ca *= (1.0f / 6.0f);
        float cb = 0.0f;
        for (int j = 0; j < 5; j++) cb += dn[j];
        cb *= (1.0f / 5.0f);
        float lkSum = 0.0f;
        int nz = 0;
        for (int g = 0; g < 6; g++)
            for (int n = 0; n < 9; n++) {
                float v = dg[g] + 1.0f - dn[n];   // MARGIN = 1.0
                if (v > 0.0f) { lkSum += v; nz++; }
            }
        float intra = 0.0f;
        for (int g = 0; g < 6; g++) intra += dg[g] - ca;
        float inter = 1.0f - fabsf(ca - cb);      // BETA = 1.0
        if (inter < 0.0f) inter = 0.0f;
        float lv = lkSum / (float)(nz + 1);
        total += lv + intra * 0.1f + inter * 0.1f; // P = R = 0.1
    }
    total *= 0.25f;
    float mx = 0.0f;                              // padded zeros dominate if all mmds < 0
    for (int p = 0; p < 9; p++) mx = fmaxf(mx, g_mmds[p]);
    out[0] = total + mx * 0.01f;                  // ALPHA = 0.01
}

// ======================= launch =======================
extern "C" void kernel_launch(void* const* d_in, const int* in_sizes, int n_in,
                              void* d_out, int out_size) {
    const float* data = (const float*)d_in[0];
    const int*   lens = (const int*)d_in[1];
    float*       out  = (float*)d_out;

    norms_kernel<<<(NWV * STEPV * TTV * 32 + 255) / 256, 256>>>(data);
    cost_kernel<<<dim3(8, 8, NPAIR), 256>>>(data, lens);
    dtw_kernel<<<NPAIR, 512>>>(lens);
    gram_kernel<<<dim3(11, 11), 256>>>(data);
    mmd_kernel<<<9, 128>>>();
    final_kernel<<<1, 32>>>(lens, out);
}

// round 3
// speedup vs baseline: 2.6946x; 2.6946x over previous
#include <cuda_runtime.h>
#include <math.h>

#define TT 512
#define DD 64
#define NPAIR 60
#define NGRP 44
#define BIGV 1000000000.0f
#define C1E 0.28853900817779268f   // log2(e)/gamma, gamma=5
#define C2L 3.4657359027997265f    // gamma*ln(2)

// -------- device scratch (zero-initialized at module load) --------
// tiled cost: addr(p,i,j) = p*512*512 + (i>>5)*(512*32) + j*32 + (i&31)
__device__ float g_costT[(size_t)NPAIR * TT * TT];   // ~63 MB
__device__ float g_norms[64 * TT];
__device__ float g_G[NGRP * NGRP];
__device__ float g_sdt[NPAIR];
__device__ float g_mmds[9];

__constant__ int c_pi[9] = {0,0,0,1,1,2,2,3,3};
__constant__ int c_pj[9] = {1,2,3,2,3,1,3,1,2};

__device__ __forceinline__ float ex2f(float x) {
    float y; asm("ex2.approx.ftz.f32 %0, %1;" : "=f"(y) : "f"(x)); return y;
}
__device__ __forceinline__ float lg2f(float x) {
    float y; asm("lg2.approx.ftz.f32 %0, %1;" : "=f"(y) : "f"(x)); return y;
}

// ======================= K0: per-row squared norms =======================
__global__ void norms_kernel(const float* __restrict__ data) {
    int gw   = (blockIdx.x * blockDim.x + threadIdx.x) >> 5;
    int lane = threadIdx.x & 31;
    if (gw >= 64 * TT) return;
    const float* row = data + (size_t)gw * DD;
    float a = row[lane], b = row[lane + 32];
    float s = a * a + b * b;
    #pragma unroll
    for (int o = 16; o > 0; o >>= 1) s += __shfl_down_sync(0xffffffffu, s, o);
    if (lane == 0) g_norms[gw] = s;
}

// ======================= K1: cost matrices (tiled output) =======================
__global__ __launch_bounds__(256) void cost_kernel(const float* __restrict__ data,
                                                   const int* __restrict__ lens) {
    int p  = blockIdx.z;
    int w  = p / 15;
    int jj = p % 15;
    int la = lens[w * 16];
    int lb = lens[w * 16 + 1 + jj];
    int row0 = blockIdx.y * 64;
    int col0 = blockIdx.x * 64;
    if (row0 >= la || col0 >= lb) return;

    const float* A = data + (size_t)(w * 16) * TT * DD;
    const float* B = data + (size_t)(w * 16 + 1 + jj) * TT * DD;

    __shared__ float As[64][65];
    __shared__ float Bs[64][65];

    int tid = threadIdx.x;
    #pragma unroll
    for (int q = 0; q < 4; q++) {
        int idx = tid + q * 256;
        int r   = idx >> 4;
        int c4  = idx & 15;
        float4 va = *(const float4*)(A + (size_t)(row0 + r) * DD + c4 * 4);
        float4 vb = *(const float4*)(B + (size_t)(col0 + r) * DD + c4 * 4);
        As[r][c4*4+0] = va.x; As[r][c4*4+1] = va.y; As[r][c4*4+2] = va.z; As[r][c4*4+3] = va.w;
        Bs[r][c4*4+0] = vb.x; Bs[r][c4*4+1] = vb.y; Bs[r][c4*4+2] = vb.z; Bs[r][c4*4+3] = vb.w;
    }
    __syncthreads();

    int tx = tid & 15, ty = tid >> 4;
    float acc[4][4];
    #pragma unroll
    for (int i = 0; i < 4; i++)
        #pragma unroll
        for (int j = 0; j < 4; j++) acc[i][j] = 0.0f;

    #pragma unroll 8
    for (int k = 0; k < 64; k++) {
        float a0 = As[ty*4+0][k], a1 = As[ty*4+1][k], a2 = As[ty*4+2][k], a3 = As[ty*4+3][k];
        float b0 = Bs[tx*4+0][k], b1 = Bs[tx*4+1][k], b2 = Bs[tx*4+2][k], b3 = Bs[tx*4+3][k];
        acc[0][0] = fmaf(a0,b0,acc[0][0]); acc[0][1] = fmaf(a0,b1,acc[0][1]);
        acc[0][2] = fmaf(a0,b2,acc[0][2]); acc[0][3] = fmaf(a0,b3,acc[0][3]);
        acc[1][0] = fmaf(a1,b0,acc[1][0]); acc[1][1] = fmaf(a1,b1,acc[1][1]);
        acc[1][2] = fmaf(a1,b2,acc[1][2]); acc[1][3] = fmaf(a1,b3,acc[1][3]);
        acc[2][0] = fmaf(a2,b0,acc[2][0]); acc[2][1] = fmaf(a2,b1,acc[2][1]);
        acc[2][2] = fmaf(a2,b2,acc[2][2]); acc[2][3] = fmaf(a2,b3,acc[2][3]);
        acc[3][0] = fmaf(a3,b0,acc[3][0]); acc[3][1] = fmaf(a3,b1,acc[3][1]);
        acc[3][2] = fmaf(a3,b2,acc[3][2]); acc[3][3] = fmaf(a3,b3,acc[3][3]);
    }

    float an[4], bn[4];
    #pragma unroll
    for (int i = 0; i < 4; i++) an[i] = g_norms[(w * 16) * TT + row0 + ty*4 + i];
    #pragma unroll
    for (int j = 0; j < 4; j++) bn[j] = g_norms[(w * 16 + 1 + jj) * TT + col0 + tx*4 + j];

    // stage result (reuse As) then write tiled-coalesced
    __syncthreads();
    #pragma unroll
    for (int i = 0; i < 4; i++)
        #pragma unroll
        for (int j = 0; j < 4; j++)
            As[ty*4 + i][tx*4 + j] = an[i] + bn[j] - 2.0f * acc[i][j];
    __syncthreads();

    float* outBase = g_costT + (size_t)p * TT * TT + (row0 >> 5) * (TT * 32) + col0 * 32;
    #pragma unroll
    for (int c = 0; c < 16; c++) {
        int idx  = tid + (c << 8);
        int lane = idx & 31;
        int colL = (idx >> 5) & 63;
        int rhi  = idx >> 11;                // 0 or 1
        outBase[rhi * (TT * 32) + colL * 32 + lane] = As[rhi * 32 + lane][colL];
    }
}

// ======================= fused: banded DTW (blocks 0..59) + Gram (60..180) =======================
__device__ __forceinline__ void loadRing(const float* __restrict__ Cp, float* ringW,
                                         int pS, int t) {
    const float4* src = (const float4*)(Cp + pS * 32);
    #pragma unroll
    for (int k = 0; k < 4; k++) {
        float4 v = src[k * 32 + t];
        int c   = 4 * k + (t >> 3);
        int rr  = (4 * t) & 31;
        int col = (pS + c) & 63;
        *(float4*)(ringW + (col << 5) + rr) = v;
    }
}

__global__ __launch_bounds__(512, 1) void fused_kernel(const float* __restrict__ data,
                                                       const int* __restrict__ lens) {
    extern __shared__ float sm[];
    if (blockIdx.x < NPAIR) {
        // ---------------- banded soft-DTW ----------------
        float* ring = sm;                 // [16 warps][64 cols][32 rows]
        float* bnd  = sm + 16 * 2048;     // [16 warps][64]
        int p  = blockIdx.x;
        int w  = threadIdx.x >> 5;
        int t  = threadIdx.x & 31;
        int wi = p / 15, jj = p % 15;
        int la = lens[wi * 16];
        int lb = lens[wi * 16 + 1 + jj];
        const float* Cp = g_costT + (size_t)p * TT * TT + w * (TT * 32);
        float* ringW = ring + w * 2048;
        int row = w * 32 + t;

        float r = BIGV, up_prev = BIGV;
        int nLocal = (lb + 46) >> 4;          // ceil((lb+31)/16)
        int nSup   = 45 + nLocal;             // 3*(16-1) band lag + sweep
        bool bandNeeded = (w * 32 < la);

        if (bandNeeded && w == 0) loadRing(Cp, ringW, 0, t);

        for (int sup = 0; sup < nSup; sup++) {
            __syncthreads();
            if (!bandNeeded) continue;
            int S = (sup - 3 * w) << 4;       // local step base
            if (S == -16) { loadRing(Cp, ringW, 0, t); continue; }
            if (S < 0 || S >= lb + 31) continue;

            int pS = S + 16;                   // prefetch next chunk of cols
            if (pS < lb) loadRing(Cp, ringW, pS, t);

            float bu[16];
            if (t == 0) {
                if (w > 0) {
                    #pragma unroll
                    for (int q = 0; q < 16; q++) bu[q] = bnd[(w - 1) * 64 + ((S + q) & 63)];
                } else {
                    #pragma unroll
                    for (int q = 0; q < 16; q++) bu[q] = BIGV;
                }
            }

            #pragma unroll
            for (int q = 0; q < 16; q++) {
                int s = S + q;
                int j = s - t;
                float d = ringW[((j & 63) << 5) + t];
                float upIn = __shfl_up_sync(0xffffffffu, r, 1);
                if (t == 0) upIn = bu[q];
                bool act = (j >= 0) & (j < lb);
                float diag = up_prev;
                if (w == 0 && t == 0 && s == 0) diag = 0.0f;
                float left = r;
                float mn = fminf(fminf(diag, upIn), left);
                float e  = ex2f((mn - diag) * C1E)
                         + ex2f((mn - upIn) * C1E)
                         + ex2f((mn - left) * C1E);
                float rn = d + mn - C2L * lg2f(e);
                if (act) r = rn;
                up_prev = upIn;
                if (act && t == 31 && w < 15) bnd[w * 64 + (j & 63)] = r;
                if (act && row == la - 1 && j == lb - 1) g_sdt[p] = r;
            }
        }
    } else {
        // ---------------- Gram of 44 group vectors ----------------
        int g  = blockIdx.x - NPAIR;         // 0..120
        int bi = g / 11, bj = g % 11;
        int tid = threadIdx.x;
        const float4* pa[4];
        const float4* pb[4];
        #pragma unroll
        for (int a = 0; a < 4; a++) {
            int ga = bi * 4 + a; int ra = (ga / 11) * 16 + (ga % 11);
            pa[a] = (const float4*)(data + (size_t)ra * TT * DD);
            int gb = bj * 4 + a; int rb = (gb / 11) * 16 + (gb % 11);
            pb[a] = (const float4*)(data + (size_t)rb * TT * DD);
        }
        float acc[4][4];
        #pragma unroll
        for (int a = 0; a < 4; a++)
            #pragma unroll
            for (int b = 0; b < 4; b++) acc[a][b] = 0.0f;

        for (int it = tid; it < TT * DD / 4; it += 512) {
            float4 xa[4], xb[4];
            #pragma unroll
            for (int a = 0; a < 4; a++) xa[a] = pa[a][it];
            #pragma unroll
            for (int b = 0; b < 4; b++) xb[b] = pb[b][it];
            #pragma unroll
            for (int a = 0; a < 4; a++)
                #pragma unroll
                for (int b = 0; b < 4; b++)
                    acc[a][b] += fmaf(xa[a].x, xb[b].x, fmaf(xa[a].y, xb[b].y,
                                 fmaf(xa[a].z, xb[b].z, xa[a].w * xb[b].w)));
        }
        #pragma unroll
        for (int a = 0; a < 4; a++)
            #pragma unroll
            for (int b = 0; b < 4; b++) {
                float v = acc[a][b];
                #pragma unroll
                for (int o = 16; o > 0; o >>= 1) v += __shfl_down_sync(0xffffffffu, v, o);
                acc[a][b] = v;
            }
        int wq = tid >> 5, lane = tid & 31;
        if (lane == 0) {
            #pragma unroll
            for (int a = 0; a < 4; a++)
                #pragma unroll
                for (int b = 0; b < 4; b++) sm[wq * 16 + a * 4 + b] = acc[a][b];
        }
        __syncthreads();
        if (tid < 16) {
            float s = 0.0f;
            #pragma unroll
            for (int ww = 0; ww < 16; ww++) s += sm[ww * 16 + tid];
            int a = tid >> 2, b = tid & 3;
            g_G[(bi * 4 + a) * NGRP + bj * 4 + b] = s;
        }
    }
}

// ======================= K4: per-pair MMD from Gram =======================
__global__ __launch_bounds__(128) void mmd_kernel() {
    int p  = blockIdx.x;
    int wa = c_pi[p], wb = c_pj[p];
    __shared__ float l2s[484];
    __shared__ float red[128];
    int tid = threadIdx.x;

    float part = 0.0f;
    for (int e = tid; e < 484; e += 128) {
        int a = e / 22, b = e % 22;
        int ga = (a < 11) ? wa * 11 + a : wb * 11 + (a - 11);
        int gb = (b < 11) ? wa * 11 + b : wb * 11 + (b - 11);
        float l2 = g_G[ga * NGRP + ga] + g_G[gb * NGRP + gb] - 2.0f * g_G[ga * NGRP + gb];
        l2s[e] = l2;
        part += l2;
    }
    red[tid] = part;
    __syncthreads();
    for (int s = 64; s > 0; s >>= 1) {
        if (tid < s) red[tid] += red[tid + s];
        __syncthreads();
    }
    float bw = red[0] / (22.0f * 22.0f - 22.0f) / 4.0f;
    __syncthreads();

    float part2 = 0.0f;
    for (int e = tid; e < 121; e += 128) {
        int u = e / 11, v = e % 11;
        float lxx = l2s[u * 22 + v];
        float lyy = l2s[(u + 11) * 22 + (v + 11)];
        float lxy = l2s[u * 22 + (v + 11)];
        float lyx = l2s[(u + 11) * 22 + v];
        float tacc = 0.0f;
        #pragma unroll
        for (int kk = 0; kk < 5; kk++) {
            float ib = 1.0f / (bw * (float)(1 << kk));
            tacc += __expf(-lxx * ib) + __expf(-lyy * ib)
                  - __expf(-lxy * ib) - __expf(-lyx * ib);
        }
        part2 += tacc;
    }
    red[tid] = part2;
    __syncthreads();
    for (int s = 64; s > 0; s >>= 1) {
        if (tid < s) red[tid] += red[tid + s];
        __syncthreads();
    }
    if (tid == 0) g_mmds[p] = red[0] / 121.0f;
}

// ======================= K5: finalize =======================
__global__ void final_kernel(const int* __restrict__ lens, float* __restrict__ out) {
    if (threadIdx.x != 0 || blockIdx.x != 0) return;
    float total = 0.0f;
    for (int w = 0; w < 4; w++) {
        float la = (float)lens[w * 16];
        float dg[6], dn[9];
        for (int j = 0; j < 15; j++) {
            float lb = (float)lens[w * 16 + 1 + j];
            float dist = g_sdt[w * 15 + j] / (la + lb);
            if (j < 6) dg[j] = dist; else dn[j - 6] = dist;
        }
        float ca = 0.0f;
        for (int j = 0; j < 6; j++) ca += dg[j];
        ca *= (1.0f / 6.0f);
        float cb = 0.0f;
        for (int j = 0; j < 5; j++) cb += dn[j];
        cb *= (1.0f / 5.0f);
        float lkSum = 0.0f;
        int nz = 0;
        for (int g = 0; g < 6; g++)
            for (int n = 0; n < 9; n++) {
                float v = dg[g] + 1.0f - dn[n];
                if (v > 0.0f) { lkSum += v; nz++; }
            }
        float intra = 0.0f;
        for (int g = 0; g < 6; g++) intra += dg[g] - ca;
        float inter = 1.0f - fabsf(ca - cb);
        if (inter < 0.0f) inter = 0.0f;
        float lv = lkSum / (float)(nz + 1);
        total += lv + intra * 0.1f + inter * 0.1f;
    }
    total *= 0.25f;
    float mx = 0.0f;
    for (int p = 0; p < 9; p++) mx = fmaxf(mx, g_mmds[p]);
    out[0] = total + mx * 0.01f;
}

// ======================= launch =======================
extern "C" void kernel_launch(void* const* d_in, const int* in_sizes, int n_in,
                              void* d_out, int out_size) {
    const float* data = (const float*)d_in[0];
    const int*   lens = (const int*)d_in[1];
    float*       out  = (float*)d_out;

    cudaFuncSetAttribute(fused_kernel, cudaFuncAttributeMaxDynamicSharedMemorySize, 135168);

    norms_kernel<<<(64 * TT * 32 + 255) / 256, 256>>>(data);
    cost_kernel<<<dim3(8, 8, NPAIR), 256>>>(data, lens);
    fused_kernel<<<NPAIR + 121, 512, 135168>>>(data, lens);
    mmd_kernel<<<9, 128>>>();
    final_kernel<<<1, 32>>>(lens, out);
}

// round 4
// speedup vs baseline: 2.7329x; 1.0142x over previous
#include <cuda_runtime.h>
#include <math.h>

#define TT 512
#define DD 64
#define NPAIR 60
#define NGRP 44
#define BIGV 1000000000.0f
#define C1E 0.28853900817779268f   // log2(e)/gamma, gamma=5
#define C2L 3.4657359027997265f    // gamma*ln(2)

// -------- device scratch --------
// tiled cost: addr(p,i,j) = p*512*512 + (i>>5)*(512*32) + j*32 + (i&31)
__device__ float g_costT[(size_t)NPAIR * TT * TT];   // ~63 MB
__device__ float g_G[NGRP * NGRP];
__device__ float g_sdt[NPAIR];

__constant__ int c_pi[9] = {0,0,0,1,1,2,2,3,3};
__constant__ int c_pj[9] = {1,2,3,2,3,1,3,1,2};

__device__ __forceinline__ float ex2f(float x) {
    float y; asm("ex2.approx.ftz.f32 %0, %1;" : "=f"(y) : "f"(x)); return y;
}
__device__ __forceinline__ float lg2f(float x) {
    float y; asm("lg2.approx.ftz.f32 %0, %1;" : "=f"(y) : "f"(x)); return y;
}

// ======================= K1: cost matrices (norms fused, tiled output) =======================
__global__ __launch_bounds__(256) void cost_kernel(const float* __restrict__ data,
                                                   const int* __restrict__ lens) {
    int p  = blockIdx.z;
    int w  = p / 15;
    int jj = p % 15;
    int la = lens[w * 16];
    int lb = lens[w * 16 + 1 + jj];
    int row0 = blockIdx.y * 64;
    int col0 = blockIdx.x * 64;
    if (row0 >= la || col0 >= lb) return;

    const float* A = data + (size_t)(w * 16) * TT * DD;
    const float* B = data + (size_t)(w * 16 + 1 + jj) * TT * DD;

    __shared__ float As[64][65];
    __shared__ float Bs[64][65];
    __shared__ float aN[64];
    __shared__ float bN[64];

    int tid = threadIdx.x;
    #pragma unroll
    for (int q = 0; q < 4; q++) {
        int idx = tid + q * 256;
        int r   = idx >> 4;
        int c4  = idx & 15;
        float4 va = *(const float4*)(A + (size_t)(row0 + r) * DD + c4 * 4);
        float4 vb = *(const float4*)(B + (size_t)(col0 + r) * DD + c4 * 4);
        As[r][c4*4+0] = va.x; As[r][c4*4+1] = va.y; As[r][c4*4+2] = va.z; As[r][c4*4+3] = va.w;
        Bs[r][c4*4+0] = vb.x; Bs[r][c4*4+1] = vb.y; Bs[r][c4*4+2] = vb.z; Bs[r][c4*4+3] = vb.w;
    }
    __syncthreads();

    // fused norms: threads 0..63 -> A rows, 64..127 -> B rows
    if (tid < 128) {
        int r = tid & 63;
        float s = 0.0f;
        if (tid < 64) {
            #pragma unroll 16
            for (int k = 0; k < 64; k++) { float v = As[r][k]; s = fmaf(v, v, s); }
            aN[r] = s;
        } else {
            #pragma unroll 16
            for (int k = 0; k < 64; k++) { float v = Bs[r][k]; s = fmaf(v, v, s); }
            bN[r] = s;
        }
    }

    int tx = tid & 15, ty = tid >> 4;
    float acc[4][4];
    #pragma unroll
    for (int i = 0; i < 4; i++)
        #pragma unroll
        for (int j = 0; j < 4; j++) acc[i][j] = 0.0f;

    #pragma unroll 8
    for (int k = 0; k < 64; k++) {
        float a0 = As[ty*4+0][k], a1 = As[ty*4+1][k], a2 = As[ty*4+2][k], a3 = As[ty*4+3][k];
        float b0 = Bs[tx*4+0][k], b1 = Bs[tx*4+1][k], b2 = Bs[tx*4+2][k], b3 = Bs[tx*4+3][k];
        acc[0][0] = fmaf(a0,b0,acc[0][0]); acc[0][1] = fmaf(a0,b1,acc[0][1]);
        acc[0][2] = fmaf(a0,b2,acc[0][2]); acc[0][3] = fmaf(a0,b3,acc[0][3]);
        acc[1][0] = fmaf(a1,b0,acc[1][0]); acc[1][1] = fmaf(a1,b1,acc[1][1]);
        acc[1][2] = fmaf(a1,b2,acc[1][2]); acc[1][3] = fmaf(a1,b3,acc[1][3]);
        acc[2][0] = fmaf(a2,b0,acc[2][0]); acc[2][1] = fmaf(a2,b1,acc[2][1]);
        acc[2][2] = fmaf(a2,b2,acc[2][2]); acc[2][3] = fmaf(a2,b3,acc[2][3]);
        acc[3][0] = fmaf(a3,b0,acc[3][0]); acc[3][1] = fmaf(a3,b1,acc[3][1]);
        acc[3][2] = fmaf(a3,b2,acc[3][2]); acc[3][3] = fmaf(a3,b3,acc[3][3]);
    }
    __syncthreads();   // aN/bN ready; As free for staging

    float an[4], bn[4];
    #pragma unroll
    for (int i = 0; i < 4; i++) an[i] = aN[ty*4 + i];
    #pragma unroll
    for (int j = 0; j < 4; j++) bn[j] = bN[tx*4 + j];

    #pragma unroll
    for (int i = 0; i < 4; i++)
        #pragma unroll
        for (int j = 0; j < 4; j++)
            As[ty*4 + i][tx*4 + j] = an[i] + bn[j] - 2.0f * acc[i][j];
    __syncthreads();

    float* outBase = g_costT + (size_t)p * TT * TT + (row0 >> 5) * (TT * 32) + col0 * 32;
    #pragma unroll
    for (int c = 0; c < 16; c++) {
        int idx  = tid + (c << 8);
        int lane = idx & 31;
        int colL = (idx >> 5) & 63;
        int rhi  = idx >> 11;                // 0 or 1
        outBase[rhi * (TT * 32) + colL * 32 + lane] = As[rhi * 32 + lane][colL];
    }
}

// ======================= fused: banded DTW (blocks 0..59) + Gram (60..180) =======================
__device__ __forceinline__ void loadRing(const float* __restrict__ Cp, float* ringW,
                                         int pS, int t) {
    const float4* src = (const float4*)(Cp + pS * 32);
    #pragma unroll
    for (int k = 0; k < 4; k++) {
        float4 v = src[k * 32 + t];
        int c   = 4 * k + (t >> 3);
        int rr  = (4 * t) & 31;
        int col = (pS + c) & 63;
        *(float4*)(ringW + (col << 5) + rr) = v;
    }
}

__global__ __launch_bounds__(512, 1) void fused_kernel(const float* __restrict__ data,
                                                       const int* __restrict__ lens) {
    extern __shared__ float sm[];
    if (blockIdx.x < NPAIR) {
        // ---------------- banded soft-DTW ----------------
        float* ring = sm;                 // [16 warps][64 cols][32 rows]
        float* bnd  = sm + 16 * 2048;     // [16 warps][64]
        int p  = blockIdx.x;
        int w  = threadIdx.x >> 5;
        int t  = threadIdx.x & 31;
        int wi = p / 15, jj = p % 15;
        int la = lens[wi * 16];
        int lb = lens[wi * 16 + 1 + jj];
        const float* Cp = g_costT + (size_t)p * TT * TT + w * (TT * 32);
        float* ringW = ring + w * 2048;
        int row = w * 32 + t;

        float r = BIGV, up_prev = BIGV;
        int nLocal = (lb + 46) >> 4;          // ceil((lb+31)/16)
        int nSup   = 45 + nLocal;             // 3*(16-1) band lag + sweep
        bool bandNeeded = (w * 32 < la);

        if (bandNeeded && w == 0) loadRing(Cp, ringW, 0, t);

        for (int sup = 0; sup < nSup; sup++) {
            __syncthreads();
            if (!bandNeeded) continue;
            int S = (sup - 3 * w) << 4;       // local step base
            if (S == -16) { loadRing(Cp, ringW, 0, t); continue; }
            if (S < 0 || S >= lb + 31) continue;

            int pS = S + 16;                   // prefetch next chunk of cols
            if (pS < lb) loadRing(Cp, ringW, pS, t);

            // prefetch this superstep's 16 cost values to registers
            float dv[16];
            #pragma unroll
            for (int q = 0; q < 16; q++) {
                int j = S + q - t;
                dv[q] = ringW[((j & 63) << 5) + t];
            }

            float bu[16];
            if (t == 0) {
                if (w > 0) {
                    #pragma unroll
                    for (int q = 0; q < 16; q++) bu[q] = bnd[(w - 1) * 64 + ((S + q) & 63)];
                } else {
                    #pragma unroll
                    for (int q = 0; q < 16; q++) bu[q] = BIGV;
                }
            }

            #pragma unroll
            for (int q = 0; q < 16; q++) {
                int s = S + q;
                int j = s - t;
                float upIn = __shfl_up_sync(0xffffffffu, r, 1);
                if (t == 0) upIn = bu[q];
                bool act = (j >= 0) & (j < lb);
                float diag = up_prev;
                if (w == 0 && t == 0 && s == 0) diag = 0.0f;
                float left = r;
                // min/median/max softmin: one MUFU fewer (ex2(0)==1 exactly)
                float mn2 = fminf(diag, upIn);
                float mx2 = fmaxf(diag, upIn);
                float mn  = fminf(mn2, left);
                float mx  = fmaxf(mx2, left);
                float md  = fmaxf(mn2, fminf(mx2, left));
                float e   = 1.0f + ex2f((mn - md) * C1E) + ex2f((mn - mx) * C1E);
                float rn  = (dv[q] + mn) - C2L * lg2f(e);
                if (act) r = rn;
                up_prev = upIn;
                if (act && t == 31 && w < 15) bnd[w * 64 + (j & 63)] = r;
            }
        }
        if (bandNeeded && row == la - 1) g_sdt[p] = r;   // frozen once j >= lb
    } else {
        // ---------------- Gram of 44 group vectors ----------------
        int g  = blockIdx.x - NPAIR;         // 0..120
        int bi = g / 11, bj = g % 11;
        int tid = threadIdx.x;
        const float4* pa[4];
        const float4* pb[4];
        #pragma unroll
        for (int a = 0; a < 4; a++) {
            int ga = bi * 4 + a; int ra = (ga / 11) * 16 + (ga % 11);
            pa[a] = (const float4*)(data + (size_t)ra * TT * DD);
            int gb = bj * 4 + a; int rb = (gb / 11) * 16 + (gb % 11);
            pb[a] = (const float4*)(data + (size_t)rb * TT * DD);
        }
        float acc[4][4];
        #pragma unroll
        for (int a = 0; a < 4; a++)
            #pragma unroll
            for (int b = 0; b < 4; b++) acc[a][b] = 0.0f;

        for (int it = tid; it < TT * DD / 4; it += 512) {
            float4 xa[4], xb[4];
            #pragma unroll
            for (int a = 0; a < 4; a++) xa[a] = pa[a][it];
            #pragma unroll
            for (int b = 0; b < 4; b++) xb[b] = pb[b][it];
            #pragma unroll
            for (int a = 0; a < 4; a++)
                #pragma unroll
                for (int b = 0; b < 4; b++)
                    acc[a][b] += fmaf(xa[a].x, xb[b].x, fmaf(xa[a].y, xb[b].y,
                                 fmaf(xa[a].z, xb[b].z, xa[a].w * xb[b].w)));
        }
        #pragma unroll
        for (int a = 0; a < 4; a++)
            #pragma unroll
            for (int b = 0; b < 4; b++) {
                float v = acc[a][b];
                #pragma unroll
                for (int o = 16; o > 0; o >>= 1) v += __shfl_down_sync(0xffffffffu, v, o);
                acc[a][b] = v;
            }
        int wq = tid >> 5, lane = tid & 31;
        if (lane == 0) {
            #pragma unroll
            for (int a = 0; a < 4; a++)
                #pragma unroll
                for (int b = 0; b < 4; b++) sm[wq * 16 + a * 4 + b] = acc[a][b];
        }
        __syncthreads();
        if (tid < 16) {
            float s = 0.0f;
            #pragma unroll
            for (int ww = 0; ww < 16; ww++) s += sm[ww * 16 + tid];
            int a = tid >> 2, b = tid & 3;
            g_G[(bi * 4 + a) * NGRP + bj * 4 + b] = s;
        }
    }
}

// ======================= K4: MMD (9 warps) + finalize, one block =======================
__global__ __launch_bounds__(512) void mmd_final_kernel(const int* __restrict__ lens,
                                                        float* __restrict__ out) {
    __shared__ float l2s[9][484];
    __shared__ float s_mmd[9];
    int tid  = threadIdx.x;
    int wp   = tid >> 5;     // warp = pair
    int lane = tid & 31;

    if (wp < 9) {
        int wa = c_pi[wp], wb = c_pj[wp];
        float part = 0.0f;
        #pragma unroll
        for (int q = 0; q < 16; q++) {
            int e = lane + q * 32;
            if (e < 484) {
                int a = e / 22, b = e % 22;
                int ga = (a < 11) ? wa * 11 + a : wb * 11 + (a - 11);
                int gb = (b < 11) ? wa * 11 + b : wb * 11 + (b - 11);
                float l2 = g_G[ga * NGRP + ga] + g_G[gb * NGRP + gb]
                         - 2.0f * g_G[ga * NGRP + gb];
                l2s[wp][e] = l2;
                part += l2;
            }
        }
        #pragma unroll
        for (int o = 16; o > 0; o >>= 1) part += __shfl_down_sync(0xffffffffu, part, o);
        float bw = __shfl_sync(0xffffffffu, part, 0) / (22.0f * 22.0f - 22.0f) / 4.0f;
        __syncwarp();

        float part2 = 0.0f;
        #pragma unroll
        for (int q = 0; q < 4; q++) {
            int e = lane + q * 32;
            if (e < 121) {
                int u = e / 11, v = e % 11;
                float lxx = l2s[wp][u * 22 + v];
                float lyy = l2s[wp][(u + 11) * 22 + (v + 11)];
                float lxy = l2s[wp][u * 22 + (v + 11)];
                float lyx = l2s[wp][(u + 11) * 22 + v];
                #pragma unroll
                for (int kk = 0; kk < 5; kk++) {
                    float ib = 1.0f / (bw * (float)(1 << kk));
                    part2 += __expf(-lxx * ib) + __expf(-lyy * ib)
                           - __expf(-lxy * ib) - __expf(-lyx * ib);
                }
            }
        }
        #pragma unroll
        for (int o = 16; o > 0; o >>= 1) part2 += __shfl_down_sync(0xffffffffu, part2, o);
        if (lane == 0) s_mmd[wp] = part2 / 121.0f;
    }
    __syncthreads();

    if (tid == 0) {
        float total = 0.0f;
        for (int w = 0; w < 4; w++) {
            float la = (float)lens[w * 16];
            float dg[6], dn[9];
            for (int j = 0; j < 15; j++) {
                float lb = (float)lens[w * 16 + 1 + j];
                float dist = g_sdt[w * 15 + j] / (la + lb);
                if (j < 6) dg[j] = dist; else dn[j - 6] = dist;
            }
            float ca = 0.0f;
            for (int j = 0; j < 6; j++) ca += dg[j];
            ca *= (1.0f / 6.0f);
            float cb = 0.0f;
            for (int j = 0; j < 5; j++) cb += dn[j];
            cb *= (1.0f / 5.0f);
            float lkSum = 0.0f;
            int nz = 0;
            for (int g = 0; g < 6; g++)
                for (int n = 0; n < 9; n++) {
                    float v = dg[g] + 1.0f - dn[n];
                    if (v > 0.0f) { lkSum += v; nz++; }
                }
            float intra = 0.0f;
            for (int g = 0; g < 6; g++) intra += dg[g] - ca;
            float inter = 1.0f - fabsf(ca - cb);
            if (inter < 0.0f) inter = 0.0f;
            total += lkSum / (float)(nz + 1) + intra * 0.1f + inter * 0.1f;
        }
        total *= 0.25f;
        float mx = 0.0f;
        for (int p = 0; p < 9; p++) mx = fmaxf(mx, s_mmd[p]);
        out[0] = total + mx * 0.01f;
    }
}

// ======================= launch =======================
extern "C" void kernel_launch(void* const* d_in, const int* in_sizes, int n_in,
                              void* d_out, int out_size) {
    const float* data = (const float*)d_in[0];
    const int*   lens = (const int*)d_in[1];
    float*       out  = (float*)d_out;

    cudaFuncSetAttribute(fused_kernel, cudaFuncAttributeMaxDynamicSharedMemorySize, 135168);

    cost_kernel<<<dim3(8, 8, NPAIR), 256>>>(data, lens);
    fused_kernel<<<NPAIR + 121, 512, 135168>>>(data, lens);
    mmd_final_kernel<<<1, 512>>>(lens, out);
}

// round 7
// speedup vs baseline: 3.2324x; 1.1828x over previous
#include <cuda_runtime.h>
#include <math.h>

#define TT 512
#define DD 64
#define NPAIR 60
#define NGRP 44
#define BIGV 1000000000.0f
#define C1E 0.28853900817779268f   // log2(e)/gamma, gamma=5
#define C2L 3.4657359027997265f    // gamma*ln(2)
#define RING 96                    // ring columns per band (covers live span 94)
#define LAG 5                      // supersteps of inter-band lag

// -------- device scratch --------
// tiled cost: addr(p,i,j) = p*512*512 + (i>>5)*(512*32) + j*32 + (i&31)
__device__ float g_costT[(size_t)NPAIR * TT * TT];   // ~63 MB
__device__ float g_G[NGRP * NGRP];
__device__ float g_sdt[NPAIR];

__constant__ int c_pi[9] = {0,0,0,1,1,2,2,3,3};
__constant__ int c_pj[9] = {1,2,3,2,3,1,3,1,2};

__device__ __forceinline__ float ex2f(float x) {
    float y; asm("ex2.approx.ftz.f32 %0, %1;" : "=f"(y) : "f"(x)); return y;
}
__device__ __forceinline__ float lg2f(float x) {
    float y; asm("lg2.approx.ftz.f32 %0, %1;" : "=f"(y) : "f"(x)); return y;
}

// softmin cell: d + softmin(a=diag, b=up, c=left); min/med/max form (ex2(0)==1)
__device__ __forceinline__ float cellf(float d, float a, float b, float c) {
    float mn2 = fminf(a, b), mx2 = fmaxf(a, b);
    float mn  = fminf(mn2, c);
    float mx  = fmaxf(mx2, c);
    float md  = fmaxf(mn2, fminf(mx2, c));
    float e   = 1.0f + ex2f((mn - md) * C1E) + ex2f((mn - mx) * C1E);
    return (d + mn) - C2L * lg2f(e);
}

// ======================= K1: cost matrices (transposed smem, tiled output) =======================
__global__ __launch_bounds__(256) void cost_kernel(const float* __restrict__ data,
                                                   const int* __restrict__ lens) {
    int p  = blockIdx.z;
    int w  = p / 15;
    int jj = p % 15;
    int la = lens[w * 16];
    int lb = lens[w * 16 + 1 + jj];
    int row0 = blockIdx.y * 64;
    int col0 = blockIdx.x * 64;
    if (row0 >= la || col0 >= lb) return;

    const float* A = data + (size_t)(w * 16) * TT * DD;
    const float* B = data + (size_t)(w * 16 + 1 + jj) * TT * DD;

    __shared__ float As[64 * 68];   // [k][row], pad 68 (k-stride)
    __shared__ float Bs[64 * 68];
    __shared__ float aN[64];
    __shared__ float bN[64];

    int tid = threadIdx.x;
    #pragma unroll
    for (int q = 0; q < 4; q++) {
        int idx = tid + q * 256;
        int r   = idx >> 4;
        int c4  = idx & 15;
        float4 va = *(const float4*)(A + (size_t)(row0 + r) * DD + c4 * 4);
        float4 vb = *(const float4*)(B + (size_t)(col0 + r) * DD + c4 * 4);
        As[(c4*4+0)*68 + r] = va.x; As[(c4*4+1)*68 + r] = va.y;
        As[(c4*4+2)*68 + r] = va.z; As[(c4*4+3)*68 + r] = va.w;
        Bs[(c4*4+0)*68 + r] = vb.x; Bs[(c4*4+1)*68 + r] = vb.y;
        Bs[(c4*4+2)*68 + r] = vb.z; Bs[(c4*4+3)*68 + r] = vb.w;
    }
    __syncthreads();

    // fused norms: threads 0..63 -> A rows, 64..127 -> B rows
    if (tid < 128) {
        int r = tid & 63;
        float s = 0.0f;
        if (tid < 64) {
            #pragma unroll 16
            for (int k = 0; k < 64; k++) { float v = As[k*68 + r]; s = fmaf(v, v, s); }
            aN[r] = s;
        } else {
            #pragma unroll 16
            for (int k = 0; k < 64; k++) { float v = Bs[k*68 + r]; s = fmaf(v, v, s); }
            bN[r] = s;
        }
    }

    int tx = tid & 15, ty = tid >> 4;
    float acc[4][4];
    #pragma unroll
    for (int i = 0; i < 4; i++)
        #pragma unroll
        for (int j = 0; j < 4; j++) acc[i][j] = 0.0f;

    #pragma unroll 8
    for (int k = 0; k < 64; k++) {
        float4 a4 = *(const float4*)&As[k*68 + ty*4];
        float4 b4 = *(const float4*)&Bs[k*68 + tx*4];
        acc[0][0] = fmaf(a4.x,b4.x,acc[0][0]); acc[0][1] = fmaf(a4.x,b4.y,acc[0][1]);
        acc[0][2] = fmaf(a4.x,b4.z,acc[0][2]); acc[0][3] = fmaf(a4.x,b4.w,acc[0][3]);
        acc[1][0] = fmaf(a4.y,b4.x,acc[1][0]); acc[1][1] = fmaf(a4.y,b4.y,acc[1][1]);
        acc[1][2] = fmaf(a4.y,b4.z,acc[1][2]); acc[1][3] = fmaf(a4.y,b4.w,acc[1][3]);
        acc[2][0] = fmaf(a4.z,b4.x,acc[2][0]); acc[2][1] = fmaf(a4.z,b4.y,acc[2][1]);
        acc[2][2] = fmaf(a4.z,b4.z,acc[2][2]); acc[2][3] = fmaf(a4.z,b4.w,acc[2][3]);
        acc[3][0] = fmaf(a4.w,b4.x,acc[3][0]); acc[3][1] = fmaf(a4.w,b4.y,acc[3][1]);
        acc[3][2] = fmaf(a4.w,b4.z,acc[3][2]); acc[3][3] = fmaf(a4.w,b4.w,acc[3][3]);
    }
    __syncthreads();   // aN/bN ready; As free for staging

    float an[4], bn[4];
    #pragma unroll
    for (int i = 0; i < 4; i++) an[i] = aN[ty*4 + i];
    #pragma unroll
    for (int j = 0; j < 4; j++) bn[j] = bN[tx*4 + j];

    float* stage = As;   // reuse as [64][65]
    #pragma unroll
    for (int i = 0; i < 4; i++)
        #pragma unroll
        for (int j = 0; j < 4; j++)
            stage[(ty*4 + i)*65 + tx*4 + j] = an[i] + bn[j] - 2.0f * acc[i][j];
    __syncthreads();

    float* outBase = g_costT + (size_t)p * TT * TT + (row0 >> 5) * (TT * 32) + col0 * 32;
    #pragma unroll
    for (int c = 0; c < 16; c++) {
        int idx  = tid + (c << 8);
        int lane = idx & 31;
        int colL = (idx >> 5) & 63;
        int rhi  = idx >> 11;                // 0 or 1
        outBase[rhi * (TT * 32) + colL * 32 + lane] = stage[(rhi * 32 + lane)*65 + colL];
    }
}

// ======================= fused: banded DTW (blocks 0..59) + Gram (60..180) =======================
// DTW: 8 consumer warps (2 rows/lane, 64-row bands) + 8 producer warps (ring prefetch).
// smem: ring 8*[96 cols][64 rows] = 192KB, bnd 8*128 = 4KB.
__global__ __launch_bounds__(512, 1) void fused_kernel(const float* __restrict__ data,
                                                       const int* __restrict__ lens) {
    extern __shared__ float sm[];
    if (blockIdx.x < NPAIR) {
        int p  = blockIdx.x;
        int wi = p / 15, jj = p % 15;
        int la = lens[wi * 16];
        int lb = lens[wi * 16 + 1 + jj];
        int nBands = (la + 63) >> 6;
        int nSup   = LAG * (nBands - 1) + ((lb + 78) >> 4);
        int wid = threadIdx.x >> 5;
        int t   = threadIdx.x & 31;
        float* bnd = sm + 8 * (RING * 64);     // [8][128]

        if (wid < 8) {
            // ---------------- consumer: 2 rows per lane ----------------
            int w = wid;
            float* ringW = sm + w * (RING * 64);
            bool activeBand = (w < nBands);
            float r0 = BIGV, r1 = BIGV, r0p = BIGV, u0p = BIGV, dprev = 0.0f;
            int row0 = w * 64 + 2 * t;
            int lag5 = LAG * w;

            for (int sup = 0; sup < nSup; sup++) {
                __syncthreads();
                if (!activeBand) continue;
                int S = (sup - lag5) << 4;
                if (S < 0 || S >= lb + 63) continue;

                float bu[16];
                if (w > 0) {
                    #pragma unroll
                    for (int q = 0; q < 16; q++) bu[q] = bnd[(w - 1) * 128 + ((S + q) & 127)];
                } else {
                    #pragma unroll
                    for (int q = 0; q < 16; q++) bu[q] = BIGV;
                }

                float2 dv[16];
                #pragma unroll
                for (int q = 0; q < 16; q++) {
                    int c0 = S + q - 2 * t;
                    int cm = c0 % RING; cm += (cm < 0) ? RING : 0;
                    dv[q] = *(const float2*)&ringW[cm * 64 + 2 * t];
                }

                #pragma unroll
                for (int q = 0; q < 16; q++) {
                    int c0 = S + q - 2 * t;
                    float u0 = __shfl_up_sync(0xffffffffu, r1, 1);
                    if (t == 0) u0 = bu[q];
                    float diag0 = u0p;
                    if (w == 0 && t == 0 && (S + q) == 0) diag0 = 0.0f;
                    float n0 = cellf(dv[q].x, diag0, u0, r0);
                    float n1 = cellf(dprev,  r0p,  r0, r1);
                    bool act0 = ((unsigned)c0 < (unsigned)lb);
                    bool act1 = ((unsigned)(c0 - 1) < (unsigned)lb);
                    r0p = r0;
                    if (act0) r0 = n0;
                    u0p = u0;
                    if (act1) r1 = n1;
                    dprev = dv[q].y;
                    if (act1 && t == 31) bnd[w * 128 + ((c0 - 1) & 127)] = r1;
                }
            }
            if (activeBand) {
                if (row0 == la - 1)     g_sdt[p] = r0;
                if (row0 + 1 == la - 1) g_sdt[p] = r1;
            }
        } else {
            // ---------------- producer: ring prefetch for band (wid-8) ----------------
            int w = wid - 8;
            float* ringP = sm + w * (RING * 64);
            const float* Cp0 = g_costT + (size_t)p * TT * TT + (2 * w) * (TT * 32);
            const float* Cp1 = Cp0 + TT * 32;
            bool activeBand = (w < nBands);
            int lag5 = LAG * w;

            // PROLOGUE (fix): band 0's columns 0..15 have no in-loop producer
            // iteration (it would be sup = -1). Load them before the loop; the
            // first __syncthreads() orders this ahead of consumer reads.
            // Bands w>0 get columns 0..15 at sup = 5w-1 inside the loop.
            if (activeBand && w == 0) {
                const float4* s0 = (const float4*)Cp0;
                const float4* s1 = (const float4*)Cp1;
                #pragma unroll
                for (int k = 0; k < 4; k++) {
                    int i = t + 32 * k;           // f4 idx 0..127
                    float4 v0 = s0[i];
                    float4 v1 = s1[i];
                    int col = (i >> 3);           // 0..15
                    int r4  = (i & 7) << 2;
                    *(float4*)&ringP[col * 64 + r4]      = v0;  // rows 0..31
                    *(float4*)&ringP[col * 64 + 32 + r4] = v1;  // rows 32..63
                }
            }

            for (int sup = 0; sup < nSup; sup++) {
                __syncthreads();
                if (!activeBand) continue;
                int cS = ((sup - lag5) << 4) + 16;
                if (cS < 0 || cS >= lb) continue;   // cS is mult of 16 -> cS <= 496, in-bounds
                const float4* s0 = (const float4*)(Cp0 + cS * 32);
                const float4* s1 = (const float4*)(Cp1 + cS * 32);
                #pragma unroll
                for (int k = 0; k < 4; k++) {
                    int i = t + 32 * k;           // f4 idx 0..127
                    float4 v0 = s0[i];
                    float4 v1 = s1[i];
                    int col = cS + (i >> 3);
                    int cm  = col % RING;
                    int r4  = (i & 7) << 2;
                    *(float4*)&ringP[cm * 64 + r4]      = v0;  // rows 0..31
                    *(float4*)&ringP[cm * 64 + 32 + r4] = v1;  // rows 32..63
                }
            }
        }
    } else {
        // ---------------- Gram of 44 group vectors ----------------
        int g  = blockIdx.x - NPAIR;         // 0..120
        int bi = g / 11, bj = g % 11;
        int tid = threadIdx.x;
        const float4* pa[4];
        const float4* pb[4];
        #pragma unroll
        for (int a = 0; a < 4; a++) {
            int ga = bi * 4 + a; int ra = (ga / 11) * 16 + (ga % 11);
            pa[a] = (const float4*)(data + (size_t)ra * TT * DD);
            int gb = bj * 4 + a; int rb = (gb / 11) * 16 + (gb % 11);
            pb[a] = (const float4*)(data + (size_t)rb * TT * DD);
        }
        float acc[4][4];
        #pragma unroll
        for (int a = 0; a < 4; a++)
            #pragma unroll
            for (int b = 0; b < 4; b++) acc[a][b] = 0.0f;

        for (int it = tid; it < TT * DD / 4; it += 512) {
            float4 xa[4], xb[4];
            #pragma unroll
            for (int a = 0; a < 4; a++) xa[a] = pa[a][it];
            #pragma unroll
            for (int b = 0; b < 4; b++) xb[b] = pb[b][it];
            #pragma unroll
            for (int a = 0; a < 4; a++)
                #pragma unroll
                for (int b = 0; b < 4; b++)
                    acc[a][b] += fmaf(xa[a].x, xb[b].x, fmaf(xa[a].y, xb[b].y,
                                 fmaf(xa[a].z, xb[b].z, xa[a].w * xb[b].w)));
        }
        #pragma unroll
        for (int a = 0; a < 4; a++)
            #pragma unroll
            for (int b = 0; b < 4; b++) {
                float v = acc[a][b];
                #pragma unroll
                for (int o = 16; o > 0; o >>= 1) v += __shfl_down_sync(0xffffffffu, v, o);
                acc[a][b] = v;
            }
        int wq = tid >> 5, lane = tid & 31;
        if (lane == 0) {
            #pragma unroll
            for (int a = 0; a < 4; a++)
                #pragma unroll
                for (int b = 0; b < 4; b++) sm[wq * 16 + a * 4 + b] = acc[a][b];
        }
        __syncthreads();
        if (tid < 16) {
            float s = 0.0f;
            #pragma unroll
            for (int ww = 0; ww < 16; ww++) s += sm[ww * 16 + tid];
            int a = tid >> 2, b = tid & 3;
            g_G[(bi * 4 + a) * NGRP + bj * 4 + b] = s;
        }
    }
}

// ======================= K4: MMD (9 warps) + finalize, one block =======================
__global__ __launch_bounds__(512) void mmd_final_kernel(const int* __restrict__ lens,
                                                        float* __restrict__ out) {
    __shared__ float l2s[9][484];
    __shared__ float s_mmd[9];
    int tid  = threadIdx.x;
    int wp   = tid >> 5;     // warp = pair
    int lane = tid & 31;

    if (wp < 9) {
        int wa = c_pi[wp], wb = c_pj[wp];
        float part = 0.0f;
        #pragma unroll
        for (int q = 0; q < 16; q++) {
            int e = lane + q * 32;
            if (e < 484) {
                int a = e / 22, b = e % 22;
                int ga = (a < 11) ? wa * 11 + a : wb * 11 + (a - 11);
                int gb = (b < 11) ? wa * 11 + b : wb * 11 + (b - 11);
                float l2 = g_G[ga * NGRP + ga] + g_G[gb * NGRP + gb]
                         - 2.0f * g_G[ga * NGRP + gb];
                l2s[wp][e] = l2;
                part += l2;
            }
        }
        #pragma unroll
        for (int o = 16; o > 0; o >>= 1) part += __shfl_down_sync(0xffffffffu, part, o);
        float bw = __shfl_sync(0xffffffffu, part, 0) / (22.0f * 22.0f - 22.0f) / 4.0f;
        __syncwarp();

        float part2 = 0.0f;
        #pragma unroll
        for (int q = 0; q < 4; q++) {
            int e = lane + q * 32;
            if (e < 121) {
                int u = e / 11, v = e % 11;
                float lxx = l2s[wp][u * 22 + v];
                float lyy = l2s[wp][(u + 11) * 22 + (v + 11)];
                float lxy = l2s[wp][u * 22 + (v + 11)];
                float lyx = l2s[wp][(u + 11) * 22 + v];
                #pragma unroll
                for (int kk = 0; kk < 5; kk++) {
                    float ib = 1.0f / (bw * (float)(1 << kk));
                    part2 += __expf(-lxx * ib) + __expf(-lyy * ib)
                           - __expf(-lxy * ib) - __expf(-lyx * ib);
                }
            }
        }
        #pragma unroll
        for (int o = 16; o > 0; o >>= 1) part2 += __shfl_down_sync(0xffffffffu, part2, o);
        if (lane == 0) s_mmd[wp] = part2 / 121.0f;
    }
    __syncthreads();

    if (tid == 0) {
        float total = 0.0f;
        for (int w = 0; w < 4; w++) {
            float la = (float)lens[w * 16];
            float dg[6], dn[9];
            for (int j = 0; j < 15; j++) {
                float lb = (float)lens[w * 16 + 1 + j];
                float dist = g_sdt[w * 15 + j] / (la + lb);
                if (j < 6) dg[j] = dist; else dn[j - 6] = dist;
            }
            float ca = 0.0f;
            for (int j = 0; j < 6; j++) ca += dg[j];
            ca *= (1.0f / 6.0f);
            float cb = 0.0f;
            for (int j = 0; j < 5; j++) cb += dn[j];
            cb *= (1.0f / 5.0f);
            float lkSum = 0.0f;
            int nz = 0;
            for (int g = 0; g < 6; g++)
                for (int n = 0; n < 9; n++) {
                    float v = dg[g] + 1.0f - dn[n];
                    if (v > 0.0f) { lkSum += v; nz++; }
                }
            float intra = 0.0f;
            for (int g = 0; g < 6; g++) intra += dg[g] - ca;
            float inter = 1.0f - fabsf(ca - cb);
            if (inter < 0.0f) inter = 0.0f;
            total += lkSum / (float)(nz + 1) + intra * 0.1f + inter * 0.1f;
        }
        total *= 0.25f;
        float mx = 0.0f;
        for (int p = 0; p < 9; p++) mx = fmaxf(mx, s_mmd[p]);
        out[0] = total + mx * 0.01f;
    }
}

// ======================= launch =======================
extern "C" void kernel_launch(void* const* d_in, const int* in_sizes, int n_in,
                              void* d_out, int out_size) {
    const float* data = (const float*)d_in[0];
    const int*   lens = (const int*)d_in[1];
    float*       out  = (float*)d_out;

    // ring 8*96*64*4 = 196608 B + bnd 8*128*4 = 4096 B
    cudaFuncSetAttribute(fused_kernel, cudaFuncAttributeMaxDynamicSharedMemorySize, 200704);

    cost_kernel<<<dim3(8, 8, NPAIR), 256>>>(data, lens);
    fused_kernel<<<NPAIR + 121, 512, 200704>>>(data, lens);
    mmd_final_kernel<<<1, 512>>>(lens, out);
}